// round 1
// baseline (speedup 1.0000x reference)
#include <cuda_runtime.h>
#include <cuda_bf16.h>
#include <math.h>

#define HE 361
#define WE 720
#define LL 37
#define HM 180
#define WM 360
#define KK 32
#define NP 37
#define EPSV 1e-8f

#define XT 8  // x-tiles per block

static const long OUT3D_N = (long)HM * WM * KK * 5;        // 10,368,000
static const long PM_N    = (long)HM * WM * KK;            //  2,073,600
#define OFF_PM  10368000L
#define OFF_PS  12441600L

// Precomputed axis interp tables + log pressure table
__device__ int   g_iy[HM];
__device__ float g_ty[HM];
__device__ int   g_ix[WM];
__device__ float g_tx[WM];
__device__ float g_logpe[NP];

__device__ __forceinline__ int ss_right(const float* __restrict__ g, int n, float v) {
    // searchsorted(side='right'): first index m with g[m] > v
    int lo = 0, hi = n;
    while (lo < hi) {
        int m = (lo + hi) >> 1;
        if (g[m] <= v) lo = m + 1; else hi = m;
    }
    return lo;
}

__global__ void prologue_kernel(const float* __restrict__ era5_lat,
                                const float* __restrict__ era5_lon,
                                const float* __restrict__ model_lat,
                                const float* __restrict__ model_lon,
                                const float* __restrict__ p_levels) {
    int t = threadIdx.x;
    if (t < HM) {
        float pt = model_lat[t];
        int i = ss_right(era5_lat, HE, pt) - 1;
        i = min(max(i, 0), HE - 2);
        g_iy[t] = i;
        g_ty[t] = (pt - era5_lat[i]) / (era5_lat[i + 1] - era5_lat[i]);
    }
    if (t < WM) {
        float pt = model_lon[t];
        int i = ss_right(era5_lon, WE, pt) - 1;
        i = min(max(i, 0), WE - 2);
        g_ix[t] = i;
        g_tx[t] = (pt - era5_lon[i]) / (era5_lon[i + 1] - era5_lon[i]);
    }
    if (t < NP) {
        g_logpe[t] = logf(p_levels[t] + EPSV);
    }
}

__global__ __launch_bounds__(KK * XT)
void era5_main_kernel(const float* __restrict__ u,
                      const float* __restrict__ v,
                      const float* __restrict__ w,
                      const float* __restrict__ T,
                      const float* __restrict__ q,
                      const float* __restrict__ ps,
                      const float* __restrict__ p_levels,
                      const float* __restrict__ a_k,
                      const float* __restrict__ b_k,
                      float* __restrict__ out) {
    __shared__ float s_lpe[NP];
    __shared__ float s_pl[NP];

    int tid = threadIdx.y * KK + threadIdx.x;
    if (tid < NP) {
        s_lpe[tid] = g_logpe[tid];
        s_pl[tid]  = p_levels[tid];
    }
    __syncthreads();

    int k = threadIdx.x;                       // 0..31 model level
    int x = blockIdx.x * XT + threadIdx.y;     // model lon index
    int y = blockIdx.y;                        // model lat index
    if (x >= WM) return;

    int   iy = g_iy[y];  float ty = g_ty[y];
    int   ix = g_ix[x];  float tx = g_tx[x];

    float w00 = (1.f - ty) * (1.f - tx);
    float w01 = (1.f - ty) * tx;
    float w10 = ty * (1.f - tx);
    float w11 = ty * tx;

    int p00 = iy * WE + ix;
    int p01 = p00 + 1;
    int p10 = p00 + WE;
    int p11 = p10 + 1;

    // surface pressure bilinear (warp-uniform -> broadcast loads)
    float psm = w00 * ps[p00] + w01 * ps[p01] + w10 * ps[p10] + w11 * ps[p11];

    int nv = ss_right(s_pl, NP, psm);          // nvalid
    bool valid = (nv >= 2);

    float p  = a_k[k] + b_k[k] * psm;          // model pressure (unmasked output)
    float lp = logf(p + EPSV);

    int idx = ss_right(s_lpe, NP, lp) - 1;
    int hi  = max(nv - 2, 0);
    idx = min(max(idx, 0), hi);

    float x0 = s_lpe[idx];
    float x1 = s_lpe[idx + 1];
    float t  = (lp - x0) / (x1 - x0);

    int c00 = p00 * LL;
    int c01 = p01 * LL;
    int c10 = p10 * LL;
    int c11 = p11 * LL;

    long obase = (((long)(y * WM + x)) * KK + k) * 5;

    const float* __restrict__ vars[5] = { u, v, w, T, q };
    float res[5];
    #pragma unroll
    for (int vi = 0; vi < 5; vi++) {
        const float* __restrict__ a = vars[vi];
        float g0 = w00 * __ldg(a + c00 + idx)     + w01 * __ldg(a + c01 + idx)
                 + w10 * __ldg(a + c10 + idx)     + w11 * __ldg(a + c11 + idx);
        float g1 = w00 * __ldg(a + c00 + idx + 1) + w01 * __ldg(a + c01 + idx + 1)
                 + w10 * __ldg(a + c10 + idx + 1) + w11 * __ldg(a + c11 + idx + 1);
        float o = g0 + t * (g1 - g0);
        if (!valid) o = 0.f;                   // mask BEFORE clip (matches reference)
        res[vi] = o;
    }
    // clips: T -> [150,350], q -> [0,0.05]
    res[3] = fminf(fmaxf(res[3], 150.f), 350.f);
    res[4] = fminf(fmaxf(res[4], 0.f), 0.05f);

    #pragma unroll
    for (int vi = 0; vi < 5; vi++)
        out[obase + vi] = res[vi];

    out[OFF_PM + ((long)(y * WM + x)) * KK + k] = p;

    if (k == 0)
        out[OFF_PS + (long)(y * WM + x)] = fminf(fmaxf(psm, 30000.f), 110000.f);
}

extern "C" void kernel_launch(void* const* d_in, const int* in_sizes, int n_in,
                              void* d_out, int out_size) {
    const float* u         = (const float*)d_in[0];
    const float* v         = (const float*)d_in[1];
    const float* w         = (const float*)d_in[2];
    const float* T         = (const float*)d_in[3];
    const float* q         = (const float*)d_in[4];
    const float* ps        = (const float*)d_in[5];
    const float* era5_lat  = (const float*)d_in[6];
    const float* era5_lon  = (const float*)d_in[7];
    const float* model_lat = (const float*)d_in[8];
    const float* model_lon = (const float*)d_in[9];
    const float* p_levels  = (const float*)d_in[10];
    const float* a_k       = (const float*)d_in[11];
    const float* b_k       = (const float*)d_in[12];
    float* out = (float*)d_out;

    prologue_kernel<<<1, 512>>>(era5_lat, era5_lon, model_lat, model_lon, p_levels);

    dim3 block(KK, XT);
    dim3 grid((WM + XT - 1) / XT, HM);
    era5_main_kernel<<<grid, block>>>(u, v, w, T, q, ps, p_levels, a_k, b_k, out);
}